// round 1
// baseline (speedup 1.0000x reference)
#include <cuda_runtime.h>

typedef unsigned long long u64;

#define NLAYERS 3
#define NWIRES 4

// alpha_re, alpha_im, beta_re, beta_im per (layer, wire)
__device__ __align__(16) float g_rot[NLAYERS * NWIRES][4];

// ---------------------------------------------------------------------------
// Precompute the 12 variational Rot(phi,theta,omega) SU(2) matrices.
// U = RZ(om) RY(th) RZ(phi) = [[a, b], [-conj(b), conj(a)]]
//   a = cos(th/2) e^{-i(phi+om)/2},  b = -sin(th/2) e^{ i(phi-om)/2}
// ---------------------------------------------------------------------------
__global__ void rot_precompute(const float* __restrict__ params) {
    int t = threadIdx.x;
    if (t < NLAYERS * NWIRES) {
        float phi = params[t * 3 + 0];
        float th  = params[t * 3 + 1];
        float om  = params[t * 3 + 2];
        float s, c;  sincosf(0.5f * th, &s, &c);
        float sa, ca; sincosf(-0.5f * (phi + om), &sa, &ca);
        float sb, cb; sincosf( 0.5f * (phi - om), &sb, &cb);
        g_rot[t][0] =  c * ca;
        g_rot[t][1] =  c * sa;
        g_rot[t][2] = -s * cb;
        g_rot[t][3] = -s * sb;
    }
}

// ---------------------------------------------------------------------------
// f32x2 packed helpers (Blackwell dual-rate FP32 path)
// ---------------------------------------------------------------------------
__device__ __forceinline__ u64 pk(float lo, float hi) {
    u64 r;
    asm("mov.b64 %0, {%1,%2};" : "=l"(r) : "f"(lo), "f"(hi));
    return r;
}
__device__ __forceinline__ void upk(u64 v, float& lo, float& hi) {
    asm("mov.b64 {%0,%1}, %2;" : "=f"(lo), "=f"(hi) : "l"(v));
}
__device__ __forceinline__ u64 f2mul(u64 a, u64 b) {
    u64 r; asm("mul.rn.f32x2 %0, %1, %2;" : "=l"(r) : "l"(a), "l"(b)); return r;
}
__device__ __forceinline__ u64 f2add(u64 a, u64 b) {
    u64 r; asm("add.rn.f32x2 %0, %1, %2;" : "=l"(r) : "l"(a), "l"(b)); return r;
}
__device__ __forceinline__ u64 f2fma(u64 a, u64 b, u64 c) {
    u64 r; asm("fma.rn.f32x2 %0, %1, %2, %3;" : "=l"(r) : "l"(a), "l"(b), "l"(c)); return r;
}
__device__ __forceinline__ u64 f2neg(u64 a) {
    return a ^ 0x8000000080000000ULL;  // sign-bit flip both lanes (ALU pipe)
}

// complex multiply (packed): (cr,ci) = (ar,ai)*(br,bi)
__device__ __forceinline__ void cmul(u64 ar, u64 ai, u64 br, u64 bi, u64& cr, u64& ci) {
    cr = f2fma(ar, br, f2neg(f2mul(ai, bi)));
    ci = f2fma(ar, bi, f2mul(ai, br));
}

// ---------------------------------------------------------------------------
// Generic SU(2) gate [[a,b],[-b*,a*]] applied on the qubit at bit MASK.
//   a' =  a x + b y
//   b' = -b* x + a* y
// ---------------------------------------------------------------------------
template<int MASK>
__device__ __forceinline__ void gate(u64* sr, u64* si, u64 ar, u64 ai, u64 br, u64 bi) {
    u64 nai = f2neg(ai), nbr = f2neg(br), nbi = f2neg(bi);
    #pragma unroll
    for (int i = 0; i < 16; ++i) {
        if (i & MASK) continue;
        const int j = i | MASK;
        u64 xr = sr[i], xi = si[i], yr = sr[j], yi = si[j];
        u64 t0 = f2fma(ar,  xr, f2fma(nai, xi, f2fma(br, yr, f2mul(nbi, yi))));  // a're
        u64 t1 = f2fma(ar,  xi, f2fma(ai,  xr, f2fma(br, yi, f2mul(bi,  yr))));  // a'im
        u64 t2 = f2fma(nbr, xr, f2fma(nbi, xi, f2fma(ar, yr, f2mul(ai,  yi))));  // b're
        u64 t3 = f2fma(bi,  xr, f2fma(nbr, xi, f2fma(ar, yi, f2mul(nai, yr))));  // b'im
        sr[i] = t0; si[i] = t1; sr[j] = t2; si[j] = t3;
    }
}

#define SWAP_AMP(a, b) do { u64 _t = sr[a]; sr[a] = sr[b]; sr[b] = _t; \
                            _t = si[a]; si[a] = si[b]; si[b] = _t; } while (0)

// ---------------------------------------------------------------------------
// Main kernel: each thread simulates 2 batch elements (f32x2 lanes).
// Wire q corresponds to bit (3-q) of the amplitude index (wire 0 = MSB).
// ---------------------------------------------------------------------------
__global__ void __launch_bounds__(256)
qenc_kernel(const float4* __restrict__ x4, float4* __restrict__ out4, int half) {
    int t = blockIdx.x * blockDim.x + threadIdx.x;
    if (t >= half) return;

    float4 xa = x4[t];
    float4 xb = x4[t + half];

    // half-angle trig for the 4 encoding angles, packed over the 2 elements
    u64 tc[4], ts[4];
    {
        float s0, c0, s1, c1;
        __sincosf(0.5f * xa.x, &s0, &c0); __sincosf(0.5f * xb.x, &s1, &c1);
        tc[0] = pk(c0, c1); ts[0] = pk(s0, s1);
        __sincosf(0.5f * xa.y, &s0, &c0); __sincosf(0.5f * xb.y, &s1, &c1);
        tc[1] = pk(c0, c1); ts[1] = pk(s0, s1);
        __sincosf(0.5f * xa.z, &s0, &c0); __sincosf(0.5f * xb.z, &s1, &c1);
        tc[2] = pk(c0, c1); ts[2] = pk(s0, s1);
        __sincosf(0.5f * xa.w, &s0, &c0); __sincosf(0.5f * xb.w, &s1, &c1);
        tc[3] = pk(c0, c1); ts[3] = pk(s0, s1);
    }

    // Encoding: all encoding gates are single-wire and commute across wires,
    // so the post-encoding state is a product state:  ⊗_i  v_i,  where
    // v_i = RY(x_{i+3}) RX(x_{i+2}) RZ(x_{i+1}) RY(x_i) |0>.
    u64 vr[4][2], vi[4][2];
    #pragma unroll
    for (int i = 0; i < 4; ++i) {
        u64 c1 = tc[i],           s1 = ts[i];
        u64 c2 = tc[(i + 1) & 3], s2 = ts[(i + 1) & 3];
        u64 c3 = tc[(i + 2) & 3], s3 = ts[(i + 2) & 3];
        u64 c4 = tc[(i + 3) & 3], s4 = ts[(i + 3) & 3];
        // after RY(x_i), RZ(x_{i+1}):  v0 = c1*e^{-i t2/2},  v1 = s1*e^{+i t2/2}
        u64 a_r = f2mul(c1, c2), a_i = f2neg(f2mul(c1, s2));
        u64 b_r = f2mul(s1, c2), b_i = f2mul(s1, s2);
        // RX(x_{i+2}): [[c,-is],[-is,c]]
        u64 ns3 = f2neg(s3);
        u64 w0r = f2fma(c3, a_r, f2mul(s3,  b_i));
        u64 w0i = f2fma(c3, a_i, f2mul(ns3, b_r));
        u64 w1r = f2fma(c3, b_r, f2mul(s3,  a_i));
        u64 w1i = f2fma(c3, b_i, f2mul(ns3, a_r));
        // RY(x_{i+3})
        u64 ns4 = f2neg(s4);
        vr[i][0] = f2fma(c4, w0r, f2mul(ns4, w1r));
        vi[i][0] = f2fma(c4, w0i, f2mul(ns4, w1i));
        vr[i][1] = f2fma(s4, w0r, f2mul(c4,  w1r));
        vi[i][1] = f2fma(s4, w0i, f2mul(c4,  w1i));
    }

    // progressive tensor product -> 16 amplitudes (index = b3 b2 b1 b0, wire0=b3)
    u64 w2r[4], w2i[4], w3r[8], w3i[8], sr[16], si[16];
    #pragma unroll
    for (int k = 0; k < 4; ++k)
        cmul(vr[0][k >> 1], vi[0][k >> 1], vr[1][k & 1], vi[1][k & 1], w2r[k], w2i[k]);
    #pragma unroll
    for (int k = 0; k < 8; ++k)
        cmul(w2r[k >> 1], w2i[k >> 1], vr[2][k & 1], vi[2][k & 1], w3r[k], w3i[k]);
    #pragma unroll
    for (int k = 0; k < 16; ++k)
        cmul(w3r[k >> 1], w3i[k >> 1], vr[3][k & 1], vi[3][k & 1], sr[k], si[k]);

    // Variational layers: 4 Rot gates (wires 0..3 -> bits 8,4,2,1), then
    // CNOT chain (pure register permutation).
    const float4* rot = reinterpret_cast<const float4*>(g_rot);
    #pragma unroll
    for (int l = 0; l < NLAYERS; ++l) {
        {
            float4 u = rot[l * 4 + 0];
            gate<8>(sr, si, pk(u.x, u.x), pk(u.y, u.y), pk(u.z, u.z), pk(u.w, u.w));
        }
        {
            float4 u = rot[l * 4 + 1];
            gate<4>(sr, si, pk(u.x, u.x), pk(u.y, u.y), pk(u.z, u.z), pk(u.w, u.w));
        }
        {
            float4 u = rot[l * 4 + 2];
            gate<2>(sr, si, pk(u.x, u.x), pk(u.y, u.y), pk(u.z, u.z), pk(u.w, u.w));
        }
        {
            float4 u = rot[l * 4 + 3];
            gate<1>(sr, si, pk(u.x, u.x), pk(u.y, u.y), pk(u.z, u.z), pk(u.w, u.w));
        }
        // CNOT(control wire0 -> target wire1): bit3=1, swap bit2 pair
        SWAP_AMP(8, 12); SWAP_AMP(9, 13); SWAP_AMP(10, 14); SWAP_AMP(11, 15);
        // CNOT(control wire1 -> target wire2): bit2=1, swap bit1 pair
        SWAP_AMP(4, 6);  SWAP_AMP(5, 7);  SWAP_AMP(12, 14); SWAP_AMP(13, 15);
        // CNOT(control wire2 -> target wire3): bit1=1, swap bit0 pair
        SWAP_AMP(2, 3);  SWAP_AMP(6, 7);  SWAP_AMP(10, 11); SWAP_AMP(14, 15);
    }

    // Pauli-Z expectations
    u64 p[16];
    #pragma unroll
    for (int k = 0; k < 16; ++k)
        p[k] = f2fma(sr[k], sr[k], f2mul(si[k], si[k]));

    u64 z[4];
    #pragma unroll
    for (int q = 0; q < 4; ++q) {
        const int m = 8 >> q;
        u64 pos = p[0];
        u64 ng  = p[m];
        #pragma unroll
        for (int k = 1; k < 16; ++k) {
            if (k == m) continue;
            if (k & m) ng = f2add(ng, p[k]);
            else       pos = f2add(pos, p[k]);
        }
        z[q] = f2add(pos, f2neg(ng));
    }

    float z0a, z0b, z1a, z1b, z2a, z2b, z3a, z3b;
    upk(z[0], z0a, z0b); upk(z[1], z1a, z1b);
    upk(z[2], z2a, z2b); upk(z[3], z3a, z3b);
    out4[t]        = make_float4(z0a, z1a, z2a, z3a);
    out4[t + half] = make_float4(z0b, z1b, z2b, z3b);
}

// ---------------------------------------------------------------------------
extern "C" void kernel_launch(void* const* d_in, const int* in_sizes, int n_in,
                              void* d_out, int out_size) {
    const float* x      = (const float*)d_in[0];   // (B, 4) float32
    const float* params = (const float*)d_in[1];   // (3, 4, 3) float32
    float* out          = (float*)d_out;           // (B, 4) float32

    int B = in_sizes[0] / 4;
    int half = B / 2;

    rot_precompute<<<1, 32>>>(params);

    int threads = 256;
    int blocks = (half + threads - 1) / threads;
    qenc_kernel<<<blocks, threads>>>((const float4*)x, (float4*)out, half);
}

// round 2
// speedup vs baseline: 1.2670x; 1.2670x over previous
#include <cuda_runtime.h>

typedef unsigned long long u64;

#define NLAYERS 3
#define NWIRES 4

// alpha_re, alpha_im, beta_re, beta_im per (layer, wire)
__device__ __align__(16) float g_rot[NLAYERS * NWIRES][4];

// ---------------------------------------------------------------------------
// Precompute the 12 variational Rot(phi,theta,omega) SU(2) matrices.
// U = RZ(om) RY(th) RZ(phi) = [[a, b], [-conj(b), conj(a)]]
//   a = cos(th/2) e^{-i(phi+om)/2},  b = -sin(th/2) e^{ i(phi-om)/2}
// ---------------------------------------------------------------------------
__global__ void rot_precompute(const float* __restrict__ params) {
    int t = threadIdx.x;
    if (t < NLAYERS * NWIRES) {
        float phi = params[t * 3 + 0];
        float th  = params[t * 3 + 1];
        float om  = params[t * 3 + 2];
        float s, c;  sincosf(0.5f * th, &s, &c);
        float sa, ca; sincosf(-0.5f * (phi + om), &sa, &ca);
        float sb, cb; sincosf( 0.5f * (phi - om), &sb, &cb);
        g_rot[t][0] =  c * ca;
        g_rot[t][1] =  c * sa;
        g_rot[t][2] = -s * cb;
        g_rot[t][3] = -s * sb;
    }
}

// ---------------------------------------------------------------------------
// f32x2 packed helpers (Blackwell dual-rate FP32 path)
// ---------------------------------------------------------------------------
__device__ __forceinline__ u64 pk(float lo, float hi) {
    u64 r;
    asm("mov.b64 %0, {%1,%2};" : "=l"(r) : "f"(lo), "f"(hi));
    return r;
}
__device__ __forceinline__ void upk(u64 v, float& lo, float& hi) {
    asm("mov.b64 {%0,%1}, %2;" : "=f"(lo), "=f"(hi) : "l"(v));
}
__device__ __forceinline__ u64 f2mul(u64 a, u64 b) {
    u64 r; asm("mul.rn.f32x2 %0, %1, %2;" : "=l"(r) : "l"(a), "l"(b)); return r;
}
__device__ __forceinline__ u64 f2add(u64 a, u64 b) {
    u64 r; asm("add.rn.f32x2 %0, %1, %2;" : "=l"(r) : "l"(a), "l"(b)); return r;
}
__device__ __forceinline__ u64 f2fma(u64 a, u64 b, u64 c) {
    u64 r; asm("fma.rn.f32x2 %0, %1, %2, %3;" : "=l"(r) : "l"(a), "l"(b), "l"(c)); return r;
}
__device__ __forceinline__ u64 f2sub(u64 a, u64 b) {
    u64 r; asm("sub.rn.f32x2 %0, %1, %2;" : "=l"(r) : "l"(a), "l"(b)); return r;
}
__device__ __forceinline__ u64 f2neg(u64 a) {
    return a ^ 0x8000000080000000ULL;  // sign-bit flip both lanes (ALU pipe)
}

// complex multiply (packed): (cr,ci) = (ar,ai)*(br,bi)
__device__ __forceinline__ void cmul(u64 ar, u64 ai, u64 br, u64 bi, u64& cr, u64& ci) {
    cr = f2fma(ar, br, f2neg(f2mul(ai, bi)));
    ci = f2fma(ar, bi, f2mul(ai, br));
}

// ---------------------------------------------------------------------------
// SU(2) gate [[a,b],[-b*,a*]] applied to one amplitude pair (x, y):
//   x' =  a x + b y
//   y' = -b* x + a* y
// 16 f32x2 FMA-pipe ops (minimal for a complex 2x2 mat-vec).
// Negated coefficients passed in so the XORs are hoisted once per gate.
// ---------------------------------------------------------------------------
__device__ __forceinline__ void su2_pair(
    u64& xr, u64& xi, u64& yr, u64& yi,
    u64 ar, u64 ai, u64 br, u64 bi,
    u64 nai, u64 nbr, u64 nbi)
{
    u64 t0 = f2fma(ar,  xr, f2fma(nai, xi, f2fma(br, yr, f2mul(nbi, yi))));
    u64 t1 = f2fma(ar,  xi, f2fma(ai,  xr, f2fma(br, yi, f2mul(bi,  yr))));
    u64 t2 = f2fma(nbr, xr, f2fma(nbi, xi, f2fma(ar, yr, f2mul(ai,  yi))));
    u64 t3 = f2fma(bi,  xr, f2fma(nbr, xi, f2fma(ar, yi, f2mul(nai, yr))));
    xr = t0; xi = t1; yr = t2; yi = t3;
}

// Full-state gate on the qubit at bit MASK (8 independent pairs -> good ILP).
template<int MASK>
__device__ __forceinline__ void gate(u64* sr, u64* si, const float4 u) {
    u64 ar = pk(u.x, u.x), ai = pk(u.y, u.y), br = pk(u.z, u.z), bi = pk(u.w, u.w);
    u64 nai = f2neg(ai), nbr = f2neg(br), nbi = f2neg(bi);
    #pragma unroll
    for (int i = 0; i < 16; ++i) {
        if (i & MASK) continue;
        const int j = i | MASK;
        su2_pair(sr[i], si[i], sr[j], si[j], ar, ai, br, bi, nai, nbr, nbi);
    }
}

#define SWAP_AMP(a, b) do { u64 _t = sr[a]; sr[a] = sr[b]; sr[b] = _t; \
                            _t = si[a]; si[a] = si[b]; si[b] = _t; } while (0)

// ---------------------------------------------------------------------------
// Main kernel: each thread simulates 2 batch elements (f32x2 lanes).
// Wire q corresponds to bit (3-q) of the amplitude index (wire 0 = MSB).
// ---------------------------------------------------------------------------
__global__ void __launch_bounds__(256)
qenc_kernel(const float4* __restrict__ x4, float4* __restrict__ out4, int half) {
    int t = blockIdx.x * blockDim.x + threadIdx.x;
    if (t >= half) return;

    float4 xa = x4[t];
    float4 xb = x4[t + half];

    // half-angle trig for the 4 encoding angles, packed over the 2 elements
    u64 tc[4], ts[4];
    {
        float s0, c0, s1, c1;
        __sincosf(0.5f * xa.x, &s0, &c0); __sincosf(0.5f * xb.x, &s1, &c1);
        tc[0] = pk(c0, c1); ts[0] = pk(s0, s1);
        __sincosf(0.5f * xa.y, &s0, &c0); __sincosf(0.5f * xb.y, &s1, &c1);
        tc[1] = pk(c0, c1); ts[1] = pk(s0, s1);
        __sincosf(0.5f * xa.z, &s0, &c0); __sincosf(0.5f * xb.z, &s1, &c1);
        tc[2] = pk(c0, c1); ts[2] = pk(s0, s1);
        __sincosf(0.5f * xa.w, &s0, &c0); __sincosf(0.5f * xb.w, &s1, &c1);
        tc[3] = pk(c0, c1); ts[3] = pk(s0, s1);
    }

    const float4* rot = reinterpret_cast<const float4*>(g_rot);

    // Encoding + LAYER-0 Rot gates, all on per-wire product factors:
    //   v_i = U_{0,i} * RY(x_{i+3}) RX(x_{i+2}) RZ(x_{i+1}) RY(x_i) |0>
    // (everything up to the first CNOT is single-qubit => state stays a
    //  product state, so layer-0 gates cost 16 ops/wire instead of 128.)
    u64 vr[4][2], vi[4][2];
    #pragma unroll
    for (int i = 0; i < 4; ++i) {
        u64 c1 = tc[i],           s1 = ts[i];
        u64 c2 = tc[(i + 1) & 3], s2 = ts[(i + 1) & 3];
        u64 c3 = tc[(i + 2) & 3], s3 = ts[(i + 2) & 3];
        u64 c4 = tc[(i + 3) & 3], s4 = ts[(i + 3) & 3];
        // after RY(x_i), RZ(x_{i+1}):  v0 = c1*e^{-i t2/2},  v1 = s1*e^{+i t2/2}
        u64 a_r = f2mul(c1, c2), a_i = f2neg(f2mul(c1, s2));
        u64 b_r = f2mul(s1, c2), b_i = f2mul(s1, s2);
        // RX(x_{i+2}): [[c,-is],[-is,c]]
        u64 ns3 = f2neg(s3);
        u64 w0r = f2fma(c3, a_r, f2mul(s3,  b_i));
        u64 w0i = f2fma(c3, a_i, f2mul(ns3, b_r));
        u64 w1r = f2fma(c3, b_r, f2mul(s3,  a_i));
        u64 w1i = f2fma(c3, b_i, f2mul(ns3, a_r));
        // RY(x_{i+3})
        u64 ns4 = f2neg(s4);
        vr[i][0] = f2fma(c4, w0r, f2mul(ns4, w1r));
        vi[i][0] = f2fma(c4, w0i, f2mul(ns4, w1i));
        vr[i][1] = f2fma(s4, w0r, f2mul(c4,  w1r));
        vi[i][1] = f2fma(s4, w0i, f2mul(c4,  w1i));
        // layer-0 Rot gate on this wire (still a product state)
        float4 u = rot[i];
        u64 ar = pk(u.x, u.x), ai = pk(u.y, u.y), br = pk(u.z, u.z), bi = pk(u.w, u.w);
        su2_pair(vr[i][0], vi[i][0], vr[i][1], vi[i][1],
                 ar, ai, br, bi, f2neg(ai), f2neg(br), f2neg(bi));
    }

    // progressive tensor product -> 16 amplitudes (index = b3 b2 b1 b0, wire0=b3)
    u64 w2r[4], w2i[4], w3r[8], w3i[8], sr[16], si[16];
    #pragma unroll
    for (int k = 0; k < 4; ++k)
        cmul(vr[0][k >> 1], vi[0][k >> 1], vr[1][k & 1], vi[1][k & 1], w2r[k], w2i[k]);
    #pragma unroll
    for (int k = 0; k < 8; ++k)
        cmul(w2r[k >> 1], w2i[k >> 1], vr[2][k & 1], vi[2][k & 1], w3r[k], w3i[k]);
    #pragma unroll
    for (int k = 0; k < 16; ++k)
        cmul(w3r[k >> 1], w3i[k >> 1], vr[3][k & 1], vi[3][k & 1], sr[k], si[k]);

    // layer-0 CNOT chain (pure register permutation, zero SASS)
    SWAP_AMP(8, 12); SWAP_AMP(9, 13); SWAP_AMP(10, 14); SWAP_AMP(11, 15);
    SWAP_AMP(4, 6);  SWAP_AMP(5, 7);  SWAP_AMP(12, 14); SWAP_AMP(13, 15);
    SWAP_AMP(2, 3);  SWAP_AMP(6, 7);  SWAP_AMP(10, 11); SWAP_AMP(14, 15);

    // Layers 1..2: full-state gates + CNOT chains
    #pragma unroll
    for (int l = 1; l < NLAYERS; ++l) {
        gate<8>(sr, si, rot[l * 4 + 0]);
        gate<4>(sr, si, rot[l * 4 + 1]);
        gate<2>(sr, si, rot[l * 4 + 2]);
        gate<1>(sr, si, rot[l * 4 + 3]);
        SWAP_AMP(8, 12); SWAP_AMP(9, 13); SWAP_AMP(10, 14); SWAP_AMP(11, 15);
        SWAP_AMP(4, 6);  SWAP_AMP(5, 7);  SWAP_AMP(12, 14); SWAP_AMP(13, 15);
        SWAP_AMP(2, 3);  SWAP_AMP(6, 7);  SWAP_AMP(10, 11); SWAP_AMP(14, 15);
    }

    // probabilities
    u64 p[16];
    #pragma unroll
    for (int k = 0; k < 16; ++k)
        p[k] = f2fma(sr[k], sr[k], f2mul(si[k], si[k]));

    // Butterfly (partial Walsh) reduction for the 4 Z expectations.
    // bit0 (mask 1) = wire 3, bit1 = wire 2, bit2 = wire 1, bit3 = wire 0.
    u64 a[8], d[8];
    #pragma unroll
    for (int k = 0; k < 8; ++k) {
        a[k] = f2add(p[2 * k], p[2 * k + 1]);
        d[k] = f2sub(p[2 * k], p[2 * k + 1]);
    }
    u64 z3 = f2add(f2add(f2add(d[0], d[1]), f2add(d[2], d[3])),
                   f2add(f2add(d[4], d[5]), f2add(d[6], d[7])));
    u64 b[4], e[4];
    #pragma unroll
    for (int k = 0; k < 4; ++k) {
        b[k] = f2add(a[2 * k], a[2 * k + 1]);
        e[k] = f2sub(a[2 * k], a[2 * k + 1]);
    }
    u64 z2 = f2add(f2add(e[0], e[1]), f2add(e[2], e[3]));
    u64 c0 = f2add(b[0], b[1]), c1 = f2add(b[2], b[3]);
    u64 z1 = f2add(f2sub(b[0], b[1]), f2sub(b[2], b[3]));
    u64 z0 = f2sub(c0, c1);

    float z0a, z0b, z1a, z1b, z2a, z2b, z3a, z3b;
    upk(z0, z0a, z0b); upk(z1, z1a, z1b);
    upk(z2, z2a, z2b); upk(z3, z3a, z3b);
    out4[t]        = make_float4(z0a, z1a, z2a, z3a);
    out4[t + half] = make_float4(z0b, z1b, z2b, z3b);
}

// ---------------------------------------------------------------------------
extern "C" void kernel_launch(void* const* d_in, const int* in_sizes, int n_in,
                              void* d_out, int out_size) {
    const float* x      = (const float*)d_in[0];   // (B, 4) float32
    const float* params = (const float*)d_in[1];   // (3, 4, 3) float32
    float* out          = (float*)d_out;           // (B, 4) float32

    int B = in_sizes[0] / 4;
    int half = B / 2;

    rot_precompute<<<1, 32>>>(params);

    int threads = 256;
    int blocks = (half + threads - 1) / threads;
    qenc_kernel<<<blocks, threads>>>((const float4*)x, (float4*)out, half);
}